// round 7
// baseline (speedup 1.0000x reference)
#include <cuda_runtime.h>
#include <cuda_fp16.h>
#include <cstdint>

#define NB      131072
#define ND      256
#define NTILES  1024         // NB / 128
#define GRID    152
#define NTHR    256
#define RS      528          // A smem row stride (256 f16 + pad) = odd*16
#define BCS     144          // B chunk row stride (128 B payload + 16 pad)
#define CHUNK_B 36864        // 256 rows * 144 B (4 kc = 64 k-cols)
#define NCH     24           // chunk-slots per tile: 3 levels * 2 passes * 4

// dynamic smem layout
#define OFF_BC  67584                      // after A (128*528)
#define OFF_W   (67584 + 3*CHUNK_B)        // 178176
#define DYN_SMEM (OFF_W + 8448)            // 186624

// ---------------- device scratch (static; no cudaMalloc) ------------------
__device__ __align__(128) __half g_Wd_chunk[3 * 4 * (CHUNK_B / 2)]; // [l][chunk][256*72]
__device__ __align__(128) __half g_Wout_img[16 * 264];
__device__ float g_bias[3][256];
__device__ float g_bout[16];

// ---------------- helpers -------------------------------------------------
static __device__ __forceinline__ uint32_t smem_u32(const void* p) {
    uint32_t a;
    asm("{ .reg .u64 t; cvta.to.shared.u64 t, %1; cvt.u32.u64 %0, t; }" : "=r"(a) : "l"(p));
    return a;
}

static __device__ __forceinline__ void ldsm4(uint32_t r[4], uint32_t addr) {
    asm volatile("ldmatrix.sync.aligned.m8n8.x4.shared.b16 {%0,%1,%2,%3}, [%4];"
                 : "=r"(r[0]), "=r"(r[1]), "=r"(r[2]), "=r"(r[3]) : "r"(addr));
}

static __device__ __forceinline__ void mma16816(float c[4], const uint32_t a[4],
                                                const uint32_t b[2]) {
    asm volatile("mma.sync.aligned.m16n8k16.row.col.f32.f16.f16.f32 "
                 "{%0,%1,%2,%3}, {%4,%5,%6,%7}, {%8,%9}, {%0,%1,%2,%3};"
                 : "+f"(c[0]), "+f"(c[1]), "+f"(c[2]), "+f"(c[3])
                 : "r"(a[0]), "r"(a[1]), "r"(a[2]), "r"(a[3]), "r"(b[0]), "r"(b[1]));
}

static __device__ __forceinline__ float tanh_f(float z) {
    float y;
    asm("tanh.approx.f32 %0, %1;" : "=f"(y) : "f"(z));
    return y;
}

#define CP_ASYNC16(dst, src) \
    asm volatile("cp.async.cg.shared.global [%0], [%1], 16;" :: "r"(dst), "l"(src) : "memory")
#define CP_COMMIT() asm volatile("cp.async.commit_group;" ::: "memory")
#define CP_WAIT1()  asm volatile("cp.async.wait_group 1;" ::: "memory")
#define CP_WAIT0()  asm volatile("cp.async.wait_group 0;" ::: "memory")

// ---------------- merged prep kernel --------------------------------------
// blocks 0..767: Wd[l][n][d] = sum_k W[l,g,k,u]*[idx==d], written into the
// chunked B image: chunk = d>>6, row n (stride 72 halfs), col d&63.
__global__ void prep_kernel(const int* __restrict__ idx, const float* __restrict__ W,
                            const float* __restrict__ W_out, const float* __restrict__ b,
                            const float* __restrict__ b_out) {
    int blk = blockIdx.x;
    int t = threadIdx.x;                    // 256 = d
    if (blk < 768) {
        __shared__ int   s_i[128];
        __shared__ float s_w[128];
        int l = blk >> 8, n = blk & 255, g = n >> 6, u = n & 63;
        if (t < 128) {
            s_i[t] = idx[(l * 4 + g) * 128 + t];
            s_w[t] = W[((l * 4 + g) * 128 + t) * 64 + u];
        }
        __syncthreads();
        float sum = 0.0f;
#pragma unroll 8
        for (int k = 0; k < 128; k++)
            if (s_i[k] == t) sum += s_w[k];
        g_Wd_chunk[(l * 4 + (t >> 6)) * (CHUNK_B / 2) + n * 72 + (t & 63)] = __float2half(sum);
    } else {
#pragma unroll
        for (int j = 0; j < 16; j++)
            g_Wout_img[j * 264 + t] = __float2half(j < 10 ? W_out[t * 10 + j] : 0.0f);
        for (int l = 0; l < 3; l++)
            g_bias[l][t] = b[(l * 4 + (t >> 6)) * 64 + (t & 63)];
        if (t < 16) g_bout[t] = (t < 10) ? b_out[t] : 0.0f;
    }
}

// ---------------- main fused kernel ---------------------------------------
__global__ __launch_bounds__(NTHR, 1)
void fused_kernel(const float* __restrict__ x, float* __restrict__ out) {
    extern __shared__ __align__(16) char dsm[];
    char* pA = dsm;
    uint32_t sA  = smem_u32(dsm);
    uint32_t sBC = sA + OFF_BC;
    uint32_t sW  = sA + OFF_W;

    __shared__ float s_bias[3][256];
    __shared__ float s_bout[16];

    int tid = threadIdx.x, wid = tid >> 5, lane = tid & 31;
    int lrow = lane & 7, sub = lane >> 3;
    uint32_t a_off    = (uint32_t)((lrow + 8 * (sub & 1)) * RS + (sub >> 1) * 16);
    uint32_t b_off144 = (uint32_t)((lrow + 8 * (sub >> 1)) * BCS + (sub & 1) * 16);
    uint32_t b_off528 = (uint32_t)((lrow + 8 * (sub >> 1)) * RS + (sub & 1) * 16);
    int n0   = (wid & 3) * 64;   // warp N-origin
    int msub = (wid >> 2) * 32;  // warp M-suborigin within a 64-row pass

    // warp-private x loader: warp wid owns rows [wid*16, wid*16+16)
    auto load_x = [&](int tt) {
        const float* xt = x + (size_t)tt * 128 * ND;
        int r0 = wid * 16;
#pragma unroll
        for (int r = 0; r < 16; r++) {
            int row = r0 + r;
            const float4* p = (const float4*)(xt + row * ND + lane * 8);
            float4 a = p[0], bq = p[1];
            __half2 h0 = __floats2half2_rn(a.x, a.y);
            __half2 h1 = __floats2half2_rn(a.z, a.w);
            __half2 h2 = __floats2half2_rn(bq.x, bq.y);
            __half2 h3 = __floats2half2_rn(bq.z, bq.w);
            *(uint4*)(pA + row * RS + lane * 16) =
                make_uint4(*(uint32_t*)&h0, *(uint32_t*)&h1,
                           *(uint32_t*)&h2, *(uint32_t*)&h3);
        }
    };

    // epilogue of one (mt, nt) accum unit: bias + tanh -> f16 pair rows
    auto epi_unit = [&](float (&def)[2][8][4], int mt, int nt, int dbase,
                        const float* dbias) {
        int row = dbase + msub + 16 * mt + (lane >> 2);
        int n   = n0 + 8 * nt + 2 * (lane & 3);
        float b0 = dbias[n], b1 = dbias[n + 1];
        float y0 = tanh_f(def[mt][nt][0] + b0);
        float y1 = tanh_f(def[mt][nt][1] + b1);
        float y2 = tanh_f(def[mt][nt][2] + b0);
        float y3 = tanh_f(def[mt][nt][3] + b1);
        __half2 h01 = __floats2half2_rn(y0, y1);
        __half2 h23 = __floats2half2_rn(y2, y3);
        *(uint32_t*)(pA + row * RS + n * 2)       = *(uint32_t*)&h01;
        *(uint32_t*)(pA + (row + 8) * RS + n * 2) = *(uint32_t*)&h23;
    };

    // ---- prologue: biases, W image, first two B chunks, first x tile -----
    s_bias[0][tid] = g_bias[0][tid];
    s_bias[1][tid] = g_bias[1][tid];
    s_bias[2][tid] = g_bias[2][tid];
    if (tid < 16) s_bout[tid] = g_bout[tid];
    {
        const char* wsrc = (const char*)g_Wout_img;
        for (int c = tid; c < 528; c += NTHR)
            CP_ASYNC16(sW + c * 16, wsrc + c * 16);
        CP_COMMIT();
        const char* bbase = (const char*)g_Wd_chunk;
#pragma unroll
        for (int i = 0; i < 9; i++)    // chunk p=0 -> stage 0
            CP_ASYNC16(sBC + (tid + i * NTHR) * 16, bbase + (tid + i * NTHR) * 16);
        CP_COMMIT();
#pragma unroll
        for (int i = 0; i < 9; i++)    // chunk p=1 -> stage 1
            CP_ASYNC16(sBC + CHUNK_B + (tid + i * NTHR) * 16,
                       bbase + CHUNK_B + (tid + i * NTHR) * 16);
        CP_COMMIT();
    }
    load_x(blockIdx.x);
    __syncthreads();

    float cA[2][8][4], cB[2][8][4];

    // one pass (64 rows) of one level, streaming 4 B chunks, with the
    // previous pass's epilogue interleaved into the chunk loop.
    auto run_seg = [&](int qbase, int pass, bool defp,
                       float (&cur)[2][8][4], float (&def)[2][8][4],
                       int dbase, const float* dbias) {
        int mb = pass * 64 + msub;
#pragma unroll
        for (int mt = 0; mt < 2; mt++)
#pragma unroll
            for (int nt = 0; nt < 8; nt++)
#pragma unroll
                for (int q = 0; q < 4; q++) cur[mt][nt][q] = 0.0f;

#pragma unroll
        for (int c = 0; c < 4; c++) {
            CP_WAIT1();            // chunk (qbase+c) resident (1 in flight)
            __syncthreads();
            // issue chunk qbase+c+2 into the stage read two iterations ago
            {
                int p2 = qbase + c + 2; if (p2 >= NCH) p2 -= NCH;
                int st2 = p2 % 3;
                const char* src = (const char*)g_Wd_chunk
                                + (size_t)((p2 >> 3) * 4 + (p2 & 3)) * CHUNK_B;
                uint32_t dst = sBC + (uint32_t)st2 * CHUNK_B;
#pragma unroll
                for (int i = 0; i < 9; i++)
                    CP_ASYNC16(dst + (tid + i * NTHR) * 16, src + (tid + i * NTHR) * 16);
                CP_COMMIT();
            }
            int p = qbase + c;
            uint32_t sb = sBC + (uint32_t)(p % 3) * CHUNK_B;
#pragma unroll
            for (int k4 = 0; k4 < 4; k4++) {
                uint32_t a[2][4], b[4][4];
#pragma unroll
                for (int mt = 0; mt < 2; mt++)
                    ldsm4(a[mt], sA + (uint32_t)((mb + 16 * mt) * RS
                                                 + (c * 4 + k4) * 32) + a_off);
#pragma unroll
                for (int bt = 0; bt < 4; bt++)
                    ldsm4(b[bt], sb + (uint32_t)((n0 + 16 * bt) * BCS + k4 * 32)
                                 + b_off144);
#pragma unroll
                for (int mt = 0; mt < 2; mt++)
#pragma unroll
                    for (int nt = 0; nt < 8; nt++)
                        mma16816(cur[mt][nt], a[mt], &b[nt >> 1][(nt & 1) * 2]);
            }
            // deferred epilogue slice (nt = 2c, 2c+1), overlaps MMA stream
            if (defp) {
                epi_unit(def, 0, 2 * c,     dbase, dbias);
                epi_unit(def, 1, 2 * c,     dbase, dbias);
                epi_unit(def, 0, 2 * c + 1, dbase, dbias);
                epi_unit(def, 1, 2 * c + 1, dbase, dbias);
            }
        }
    };

    for (int t = blockIdx.x; t < NTILES; t += GRID) {
        for (int l = 0; l < 3; l++) {
            // pass0 (rows 0-63): interleave epi1 of level l-1 (rows 64-127)
            run_seg(l * 8,     0, l > 0, cA, cB, 64, s_bias[l > 0 ? l - 1 : 0]);
            // pass1 (rows 64-127): interleave epi0 of level l (rows 0-63)
            run_seg(l * 8 + 4, 1, true,  cB, cA, 0,  s_bias[l]);
        }
        __syncthreads();   // all pass1-l2 GEMM reads of rows 64-127 done

        // standalone epilogue: epi1 of level 2 (cB -> h3 rows 64-127)
#pragma unroll
        for (int mt = 0; mt < 2; mt++)
#pragma unroll
            for (int nt = 0; nt < 8; nt++)
                epi_unit(cB, mt, nt, 64, s_bias[2]);
        __syncthreads();   // h3 complete

        // ---- final layer: out = h3 @ W_out + b_out (warp-per-16-rows) ---
        {
            float cf[2][4];
#pragma unroll
            for (int nt = 0; nt < 2; nt++)
#pragma unroll
                for (int q = 0; q < 4; q++) cf[nt][q] = 0.0f;
            int m0f = wid * 16;
#pragma unroll
            for (int kc = 0; kc < 16; kc++) {
                uint32_t a[4], b[4];
                ldsm4(a, sA + (uint32_t)(m0f * RS + kc * 32) + a_off);
                ldsm4(b, sW + (uint32_t)(kc * 32) + b_off528);
                mma16816(cf[0], a, &b[0]);
                mma16816(cf[1], a, &b[2]);
            }
            float* po0 = out + ((size_t)t * 128 + m0f + (lane >> 2)) * 10;
            float* po1 = po0 + 80;   // +8 rows
#pragma unroll
            for (int nt = 0; nt < 2; nt++) {
                int n8 = nt * 8 + 2 * (lane & 3);
                if (n8 < 10) {
                    po0[n8] = cf[nt][0] + s_bout[n8];
                    po1[n8] = cf[nt][2] + s_bout[n8];
                }
                if (n8 + 1 < 10) {
                    po0[n8 + 1] = cf[nt][1] + s_bout[n8 + 1];
                    po1[n8 + 1] = cf[nt][3] + s_bout[n8 + 1];
                }
            }
        }

        // next x tile into this warp's private rows (safe: warp-exclusive)
        if (t + GRID < NTILES) load_x(t + GRID);
        __syncthreads();
    }
    CP_WAIT0();
}

// ---------------- launch ----------------------------------------------------
extern "C" void kernel_launch(void* const* d_in, const int* in_sizes, int n_in,
                              void* d_out, int out_size) {
    const float* x     = (const float*)d_in[0];
    const int*   idx   = (const int*)  d_in[1];
    const float* W     = (const float*)d_in[2];
    const float* b     = (const float*)d_in[3];
    const float* W_out = (const float*)d_in[4];
    const float* b_out = (const float*)d_in[5];
    float* out = (float*)d_out;

    cudaFuncSetAttribute(fused_kernel, cudaFuncAttributeMaxDynamicSharedMemorySize, DYN_SMEM);

    prep_kernel<<<769, 256>>>(idx, W, W_out, b, b_out);
    fused_kernel<<<GRID, NTHR, DYN_SMEM>>>(x, out);
}

// round 9
// speedup vs baseline: 1.1129x; 1.1129x over previous
#include <cuda_runtime.h>
#include <cuda_fp16.h>
#include <cstdint>

#define NB      131072
#define ND      256
#define NTILES  1024         // NB / 128
#define GRID    152
#define NTHR    256
#define RS      528          // A smem row stride (256 f16 + pad) = odd*16
#define BHS     272          // B half row stride (128 f16 + 16B pad) = odd*16
#define CHB     69632        // bytes per B K-half: 256 rows * 272 B

// dynamic smem layout
#define OFF_B   67584                 // after A (128*528)
#define OFF_W   (OFF_B + 2*CHB)      // 206848
#define DYN_SMEM (OFF_W + 8448)      // 215296

// ---------------- device scratch (static; no cudaMalloc) ------------------
__device__ __align__(128) __half g_Wd_half[6][34816];  // [l*2+half][256n x 136]
__device__ __align__(128) __half g_Wout_img[16 * 264];
__device__ float g_bias[3][256];
__device__ float g_bout[16];

// ---------------- helpers -------------------------------------------------
static __device__ __forceinline__ uint32_t smem_u32(const void* p) {
    uint32_t a;
    asm("{ .reg .u64 t; cvta.to.shared.u64 t, %1; cvt.u32.u64 %0, t; }" : "=r"(a) : "l"(p));
    return a;
}

static __device__ __forceinline__ void ldsm4(uint32_t r[4], uint32_t addr) {
    asm volatile("ldmatrix.sync.aligned.m8n8.x4.shared.b16 {%0,%1,%2,%3}, [%4];"
                 : "=r"(r[0]), "=r"(r[1]), "=r"(r[2]), "=r"(r[3]) : "r"(addr));
}

static __device__ __forceinline__ void mma16816(float c[4], const uint32_t a[4],
                                                const uint32_t b[2]) {
    asm volatile("mma.sync.aligned.m16n8k16.row.col.f32.f16.f16.f32 "
                 "{%0,%1,%2,%3}, {%4,%5,%6,%7}, {%8,%9}, {%0,%1,%2,%3};"
                 : "+f"(c[0]), "+f"(c[1]), "+f"(c[2]), "+f"(c[3])
                 : "r"(a[0]), "r"(a[1]), "r"(a[2]), "r"(a[3]), "r"(b[0]), "r"(b[1]));
}

static __device__ __forceinline__ float tanh_f(float z) {
    float y;
    asm("tanh.approx.f32 %0, %1;" : "=f"(y) : "f"(z));
    return y;
}

#define CP_ASYNC16(dst, src) \
    asm volatile("cp.async.cg.shared.global [%0], [%1], 16;" :: "r"(dst), "l"(src) : "memory")
#define CP_COMMIT() asm volatile("cp.async.commit_group;" ::: "memory")
#define CP_WAIT1()  asm volatile("cp.async.wait_group 1;" ::: "memory")
#define CP_WAIT0()  asm volatile("cp.async.wait_group 0;" ::: "memory")

// ---------------- merged prep kernel --------------------------------------
// blocks 0..767: Wd[l][n][d] = sum_k W[l,g,k,u]*[idx==d], written into K-half
// images: half = d>>7, within-half col dk = d&127 (row stride 136 halfs).
__global__ void prep_kernel(const int* __restrict__ idx, const float* __restrict__ W,
                            const float* __restrict__ W_out, const float* __restrict__ b,
                            const float* __restrict__ b_out) {
    int blk = blockIdx.x;
    int t = threadIdx.x;                    // 256 = d
    if (blk < 768) {
        __shared__ int   s_i[128];
        __shared__ float s_w[128];
        int l = blk >> 8, n = blk & 255, g = n >> 6, u = n & 63;
        if (t < 128) {
            s_i[t] = idx[(l * 4 + g) * 128 + t];
            s_w[t] = W[((l * 4 + g) * 128 + t) * 64 + u];
        }
        __syncthreads();
        float sum = 0.0f;
#pragma unroll 8
        for (int k = 0; k < 128; k++)
            if (s_i[k] == t) sum += s_w[k];
        g_Wd_half[l * 2 + (t >> 7)][n * 136 + (t & 127)] = __float2half(sum);
    } else {
#pragma unroll
        for (int j = 0; j < 16; j++)
            g_Wout_img[j * 264 + t] = __float2half(j < 10 ? W_out[t * 10 + j] : 0.0f);
        for (int l = 0; l < 3; l++)
            g_bias[l][t] = b[(l * 4 + (t >> 6)) * 64 + (t & 63)];
        if (t < 16) g_bout[t] = (t < 10) ? b_out[t] : 0.0f;
    }
}

// ---------------- main fused kernel ---------------------------------------
__global__ __launch_bounds__(NTHR, 1)
void fused_kernel(const float* __restrict__ x, float* __restrict__ out) {
    extern __shared__ __align__(16) char dsm[];
    char* pA = dsm;
    uint32_t sA  = smem_u32(dsm);
    uint32_t sB0 = sA + OFF_B;
    uint32_t sB1 = sB0 + CHB;
    uint32_t sW  = sA + OFF_W;

    __shared__ float s_bias[3][256];
    __shared__ float s_bout[16];

    int tid = threadIdx.x, wid = tid >> 5, lane = tid & 31;
    int lrow = lane & 7, sub = lane >> 3;
    uint32_t a_off    = (uint32_t)((lrow + 8 * (sub & 1)) * RS + (sub >> 1) * 16);
    uint32_t b_offH   = (uint32_t)((lrow + 8 * (sub >> 1)) * BHS + (sub & 1) * 16);
    uint32_t b_off528 = (uint32_t)((lrow + 8 * (sub >> 1)) * RS + (sub & 1) * 16);
    int n0   = (wid & 3) * 64;    // warp N-origin
    int msub = (wid >> 2) * 32;   // warp M-suborigin within a 64-row pass

    // issue one B K-half chunk (ci = l*2+half); stage = half = ci&1
    auto issue_chunk = [&](int ci) {
        const char* src = (const char*)g_Wd_half[ci];
        uint32_t dst = (ci & 1) ? sB1 : sB0;
#pragma unroll
        for (int i = 0; i < 17; i++) {
            int c = tid + i * NTHR;            // 4352 chunks of 16 B
            CP_ASYNC16(dst + c * 16, src + c * 16);
        }
        CP_COMMIT();
    };

    // warp-private x loader: warp wid owns rows [wid*16, wid*16+16)
    auto load_x = [&](int tt) {
        const float* xt = x + (size_t)tt * 128 * ND;
        int r0 = wid * 16;
#pragma unroll
        for (int r = 0; r < 16; r++) {
            int row = r0 + r;
            const float4* p = (const float4*)(xt + row * ND + lane * 8);
            float4 a = p[0], bq = p[1];
            __half2 h0 = __floats2half2_rn(a.x, a.y);
            __half2 h1 = __floats2half2_rn(a.z, a.w);
            __half2 h2 = __floats2half2_rn(bq.x, bq.y);
            __half2 h3 = __floats2half2_rn(bq.z, bq.w);
            *(uint4*)(pA + row * RS + lane * 16) =
                make_uint4(*(uint32_t*)&h0, *(uint32_t*)&h1,
                           *(uint32_t*)&h2, *(uint32_t*)&h3);
        }
    };

    // epilogue of one (mt, nt) unit of a deferred accum: bias+tanh -> f16 -> A
    auto epi_unit = [&](float (&def)[2][8][4], int mt, int nt, int dbase,
                        const float* dbias) {
        int row = dbase + msub + 16 * mt + (lane >> 2);
        int n   = n0 + 8 * nt + 2 * (lane & 3);
        float b0 = dbias[n], b1 = dbias[n + 1];
        float y0 = tanh_f(def[mt][nt][0] + b0);
        float y1 = tanh_f(def[mt][nt][1] + b1);
        float y2 = tanh_f(def[mt][nt][2] + b0);
        float y3 = tanh_f(def[mt][nt][3] + b1);
        __half2 h01 = __floats2half2_rn(y0, y1);
        __half2 h23 = __floats2half2_rn(y2, y3);
        *(uint32_t*)(pA + row * RS + n * 2)       = *(uint32_t*)&h01;
        *(uint32_t*)(pA + (row + 8) * RS + n * 2) = *(uint32_t*)&h23;
    };

    // one K-half of one pass: 8 kc on stage sb, with optional deferred epi
    // units (kc0..kc0+7) interleaved into the MMA stream.
    auto half_pass = [&](int mbase, int kc0, uint32_t sb, float (&cur)[2][8][4],
                         float (*def)[2][8][4], int dbase, const float* dbias) {
#pragma unroll
        for (int kci = 0; kci < 8; kci++) {
            int kc = kc0 + kci;
            uint32_t a[2][4], b[4][4];
#pragma unroll
            for (int mt = 0; mt < 2; mt++)
                ldsm4(a[mt], sA + (uint32_t)((mbase + 16 * mt) * RS + kc * 32) + a_off);
#pragma unroll
            for (int bt = 0; bt < 4; bt++)
                ldsm4(b[bt], sb + (uint32_t)((n0 + 16 * bt) * BHS + kci * 32) + b_offH);
#pragma unroll
            for (int mt = 0; mt < 2; mt++)
#pragma unroll
                for (int nt = 0; nt < 8; nt++)
                    mma16816(cur[mt][nt], a[mt], &b[nt >> 1][(nt & 1) * 2]);
            if (def) epi_unit(*def, kc >> 3, kc & 7, dbase, dbias);
        }
    };

    // ---- prologue --------------------------------------------------------
    s_bias[0][tid] = g_bias[0][tid];
    s_bias[1][tid] = g_bias[1][tid];
    s_bias[2][tid] = g_bias[2][tid];
    if (tid < 16) s_bout[tid] = g_bout[tid];
    {
        const char* wsrc = (const char*)g_Wout_img;
        for (int c = tid; c < 528; c += NTHR)
            CP_ASYNC16(sW + c * 16, wsrc + c * 16);
        CP_COMMIT();                 // G: W image
    }
    issue_chunk(0);                  // (l0, k0) -> stage0
    load_x(blockIdx.x);

    float cA[2][8][4], cB[2][8][4];
    int ci = 1;                      // next chunk to issue (mod 6)

    for (int t = blockIdx.x; t < NTILES; t += GRID) {
        for (int l = 0; l < 3; l++) {
            __syncthreads();                       // S_A: stage1 free (+x/epi vis)
            issue_chunk(ci); ci = (ci == 5) ? 0 : ci + 1;   // (l, k1) -> stage1
            CP_WAIT1();                            // (l, k0) resident
            __syncthreads();                       // S_B: publish stage0

            // ---- pass0: rows 0-63; interleave epi of prev level rows 64-127
#pragma unroll
            for (int mt = 0; mt < 2; mt++)
#pragma unroll
                for (int nt = 0; nt < 8; nt++)
#pragma unroll
                    for (int q = 0; q < 4; q++) cA[mt][nt][q] = 0.0f;
            if (l > 0)
                half_pass(msub, 0, sB0, cA, &cB, 64, s_bias[l - 1]);
            else
                half_pass(msub, 0, sB0, cA, nullptr, 0, s_bias[0]);
            CP_WAIT0();                            // (l, k1) resident
            __syncthreads();                       // S_C: publish stage1
            if (l > 0)
                half_pass(msub, 8, sB1, cA, &cB, 64, s_bias[l - 1]);
            else
                half_pass(msub, 8, sB1, cA, nullptr, 0, s_bias[0]);
            __syncthreads();                       // S_D: epi(rows64-127) done

            // ---- pass1: rows 64-127; interleave epi of this level rows 0-63
#pragma unroll
            for (int mt = 0; mt < 2; mt++)
#pragma unroll
                for (int nt = 0; nt < 8; nt++)
#pragma unroll
                    for (int q = 0; q < 4; q++) cB[mt][nt][q] = 0.0f;
            half_pass(64 + msub, 0, sB0, cB, &cA, 0, s_bias[l]);
            __syncthreads();                       // S_E: all warps done stage0
            issue_chunk(ci); ci = (ci == 5) ? 0 : ci + 1;   // (l+1, k0) -> stage0
            half_pass(64 + msub, 8, sB1, cB, &cA, 0, s_bias[l]);
        }

        __syncthreads();                           // pass1-l2 reads done
        // standalone epilogue: level2 rows 64-127 (cB)
#pragma unroll
        for (int u = 0; u < 16; u++)
            epi_unit(cB, u >> 3, u & 7, 64, s_bias[2]);
        __syncthreads();                           // h3 complete

        // ---- final layer: out = h3 @ W_out + b_out (warp-per-16-rows) ----
        {
            float cf[2][4];
#pragma unroll
            for (int nt = 0; nt < 2; nt++)
#pragma unroll
                for (int q = 0; q < 4; q++) cf[nt][q] = 0.0f;
            int m0f = wid * 16;
#pragma unroll
            for (int kc = 0; kc < 16; kc++) {
                uint32_t a[4], b[4];
                ldsm4(a, sA + (uint32_t)(m0f * RS + kc * 32) + a_off);
                ldsm4(b, sW + (uint32_t)(kc * 32) + b_off528);
                mma16816(cf[0], a, &b[0]);
                mma16816(cf[1], a, &b[2]);
            }
            float* po0 = out + ((size_t)t * 128 + m0f + (lane >> 2)) * 10;
            float* po1 = po0 + 80;   // +8 rows
#pragma unroll
            for (int nt = 0; nt < 2; nt++) {
                int n8 = nt * 8 + 2 * (lane & 3);
                if (n8 < 10) {
                    po0[n8] = cf[nt][0] + s_bout[n8];
                    po1[n8] = cf[nt][2] + s_bout[n8];
                }
                if (n8 + 1 < 10) {
                    po0[n8 + 1] = cf[nt][1] + s_bout[n8 + 1];
                    po1[n8 + 1] = cf[nt][3] + s_bout[n8 + 1];
                }
            }
        }

        // next x tile into this warp's private rows (safe: warp-exclusive;
        // published by next iteration's S_A)
        if (t + GRID < NTILES) load_x(t + GRID);
    }
    CP_WAIT0();
}

// ---------------- launch ----------------------------------------------------
extern "C" void kernel_launch(void* const* d_in, const int* in_sizes, int n_in,
                              void* d_out, int out_size) {
    const float* x     = (const float*)d_in[0];
    const int*   idx   = (const int*)  d_in[1];
    const float* W     = (const float*)d_in[2];
    const float* b     = (const float*)d_in[3];
    const float* W_out = (const float*)d_in[4];
    const float* b_out = (const float*)d_in[5];
    float* out = (float*)d_out;

    cudaFuncSetAttribute(fused_kernel, cudaFuncAttributeMaxDynamicSharedMemorySize, DYN_SMEM);

    prep_kernel<<<769, 256>>>(idx, W, W_out, b, b_out);
    fused_kernel<<<GRID, NTHR, DYN_SMEM>>>(x, out);
}

// round 12
// speedup vs baseline: 1.2215x; 1.0975x over previous
#include <cuda_runtime.h>
#include <cuda_fp16.h>
#include <cstdint>

#define NB      131072
#define ND      256
#define NTILES  1024         // NB / 128
#define GRID    152
#define NTHR    256
#define RS      528          // A/h smem row stride (256 f16 + pad) = odd*16
#define BS2     272          // B' row stride (128 f16 + 16B pad) = odd*16
#define CHB     69632        // bytes per level B' image: 256 rows * 272

// dynamic smem layout
#define OFF_B   67584                 // after A (128*528)
#define OFF_W   (OFF_B + 2*CHB)      // 206848
#define DYN_SMEM (OFF_W + 8448)      // 215296

// ---------------- device scratch (static; no cudaMalloc) ------------------
__device__ __align__(128) __half   g_Bimg[3][256 * 136]; // [l][(g*64+u)*136 + k]
__device__ __align__(128) __half   g_Wout_img[16 * 264];
__device__ __align__(16)  uint16_t g_boff[1536];         // 2*idx[l][g][k]
__device__ float g_bias[3][256];
__device__ float g_bout[16];

// ---------------- helpers -------------------------------------------------
static __device__ __forceinline__ uint32_t smem_u32(const void* p) {
    uint32_t a;
    asm("{ .reg .u64 t; cvta.to.shared.u64 t, %1; cvt.u32.u64 %0, t; }" : "=r"(a) : "l"(p));
    return a;
}

static __device__ __forceinline__ void ldsm4(uint32_t r[4], uint32_t addr) {
    asm volatile("ldmatrix.sync.aligned.m8n8.x4.shared.b16 {%0,%1,%2,%3}, [%4];"
                 : "=r"(r[0]), "=r"(r[1]), "=r"(r[2]), "=r"(r[3]) : "r"(addr));
}

static __device__ __forceinline__ void mma16816(float c[4], const uint32_t a[4],
                                                const uint32_t b[2]) {
    asm volatile("mma.sync.aligned.m16n8k16.row.col.f32.f16.f16.f32 "
                 "{%0,%1,%2,%3}, {%4,%5,%6,%7}, {%8,%9}, {%0,%1,%2,%3};"
                 : "+f"(c[0]), "+f"(c[1]), "+f"(c[2]), "+f"(c[3])
                 : "r"(a[0]), "r"(a[1]), "r"(a[2]), "r"(a[3]), "r"(b[0]), "r"(b[1]));
}

static __device__ __forceinline__ float tanh_f(float z) {
    float y;
    asm("tanh.approx.f32 %0, %1;" : "=f"(y) : "f"(z));
    return y;
}

#define CP_ASYNC16(dst, src) \
    asm volatile("cp.async.cg.shared.global [%0], [%1], 16;" :: "r"(dst), "l"(src) : "memory")
#define CP_COMMIT() asm volatile("cp.async.commit_group;" ::: "memory")
#define CP_WAIT1()  asm volatile("cp.async.wait_group 1;" ::: "memory")
#define CP_WAIT0()  asm volatile("cp.async.wait_group 0;" ::: "memory")

// ---------------- merged prep kernel --------------------------------------
// blocks 0..767: B' image row: B[l][g*64+u][k] = f16(W[l,g,k,u])
// block 768: Wout image + biases + gather-offset table (2*idx)
__global__ void prep_kernel(const int* __restrict__ idx, const float* __restrict__ W,
                            const float* __restrict__ W_out, const float* __restrict__ b,
                            const float* __restrict__ b_out) {
    int blk = blockIdx.x;
    int t = threadIdx.x;                    // 256
    if (blk < 768) {
        int l = blk >> 8, n = blk & 255, g = n >> 6, u = n & 63;
        if (t < 128)
            g_Bimg[l][n * 136 + t] = __float2half(W[((l * 4 + g) * 128 + t) * 64 + u]);
    } else {
#pragma unroll
        for (int j = 0; j < 16; j++)
            g_Wout_img[j * 264 + t] = __float2half(j < 10 ? W_out[t * 10 + j] : 0.0f);
        for (int l = 0; l < 3; l++)
            g_bias[l][t] = b[(l * 4 + (t >> 6)) * 64 + (t & 63)];
        if (t < 16) g_bout[t] = (t < 10) ? b_out[t] : 0.0f;
        for (int e = t; e < 1536; e += 256)
            g_boff[e] = (uint16_t)(idx[e] * 2);
    }
}

// ---------------- main fused kernel ---------------------------------------
__global__ __launch_bounds__(NTHR, 1)
void fused_kernel(const float* __restrict__ x, float* __restrict__ out) {
    extern __shared__ __align__(16) char dsm[];
    char* pA = dsm;
    uint32_t sA  = smem_u32(dsm);
    uint32_t sB0 = sA + OFF_B;
    uint32_t sW  = sA + OFF_W;

    __shared__ float    s_bias[3][256];
    __shared__ float    s_bout[16];
    __shared__ __align__(4) uint16_t s_boff[1536];

    int tid = threadIdx.x, wid = tid >> 5, lane = tid & 31;
    int lrow = lane & 7, sub = lane >> 3;
    uint32_t b_offB   = (uint32_t)((lrow + 8 * (sub >> 1)) * BS2 + (sub & 1) * 16);
    uint32_t a_off528 = (uint32_t)((lrow + 8 * (sub & 1)) * RS + (sub >> 1) * 16);
    uint32_t b_off528 = (uint32_t)((lrow + 8 * (sub >> 1)) * RS + (sub & 1) * 16);

    int g    = wid & 3;           // group (N block: cols g*64..+64)
    int msub = (wid >> 2) * 32;   // M suborigin within a 64-row pass
    int qr   = lane >> 2;         // quad row
    int qc2  = (lane & 3) * 2;    // quad col pair base

    // issue B' level image ci%3 into stage ci%2
    auto issue_B = [&](int ci) {
        const char* src = (const char*)g_Bimg[ci % 3];
        uint32_t dst = sB0 + (uint32_t)(ci & 1) * CHB;
#pragma unroll
        for (int i = 0; i < 17; i++) {
            int c = tid + i * NTHR;            // 4352 chunks of 16 B
            CP_ASYNC16(dst + c * 16, src + c * 16);
        }
        CP_COMMIT();
    };

    // warp-private x loader: warp wid owns rows [wid*16, wid*16+16)
    auto load_x = [&](int tt) {
        const float* xt = x + (size_t)tt * 128 * ND;
        int r0 = wid * 16;
#pragma unroll
        for (int r = 0; r < 16; r++) {
            int row = r0 + r;
            const float4* p = (const float4*)(xt + row * ND + lane * 8);
            float4 a = p[0], bq = p[1];
            __half2 h0 = __floats2half2_rn(a.x, a.y);
            __half2 h1 = __floats2half2_rn(a.z, a.w);
            __half2 h2 = __floats2half2_rn(bq.x, bq.y);
            __half2 h3 = __floats2half2_rn(bq.z, bq.w);
            *(uint4*)(pA + row * RS + lane * 16) =
                make_uint4(*(uint32_t*)&h0, *(uint32_t*)&h1,
                           *(uint32_t*)&h2, *(uint32_t*)&h3);
        }
    };

    // epilogue of one (mt, nt) unit: bias + tanh -> f16 -> h rows in A
    auto epi_unit = [&](float (&def)[2][8][4], int mt, int nt, int dbase,
                        const float* dbias) {
        int row = dbase + msub + 16 * mt + qr;
        int n   = g * 64 + 8 * nt + qc2;
        float b0 = dbias[n], b1 = dbias[n + 1];
        float y0 = tanh_f(def[mt][nt][0] + b0);
        float y1 = tanh_f(def[mt][nt][1] + b1);
        float y2 = tanh_f(def[mt][nt][2] + b0);
        float y3 = tanh_f(def[mt][nt][3] + b1);
        __half2 h01 = __floats2half2_rn(y0, y1);
        __half2 h23 = __floats2half2_rn(y2, y3);
        *(uint32_t*)(pA + row * RS + n * 2)       = *(uint32_t*)&h01;
        *(uint32_t*)(pA + (row + 8) * RS + n * 2) = *(uint32_t*)&h23;
    };

    // one pass: rows [pbase, pbase+64), K=128 (8 kci) of level l on stage sb.
    // Gathers A-fragments directly from h via the offset table; optionally
    // interleaves 2 deferred epilogue units per kci.
    auto run_pass = [&](int l, int pbase, uint32_t sb, float (&cur)[2][8][4],
                        float (*def)[2][8][4], int dbase, const float* dbias) {
        const uint16_t* bo_base = s_boff + l * 512 + g * 128 + qc2;
#pragma unroll
        for (int mt = 0; mt < 2; mt++)
#pragma unroll
            for (int nt = 0; nt < 8; nt++)
#pragma unroll
                for (int q = 0; q < 4; q++) cur[mt][nt][q] = 0.0f;
#pragma unroll
        for (int kci = 0; kci < 8; kci++) {
            // gather offsets for this kci: cols k0,k0+1 and k0+8,k0+9
            uint32_t p01 = *(const uint32_t*)(bo_base + kci * 16);
            uint32_t p89 = *(const uint32_t*)(bo_base + kci * 16 + 8);
            uint32_t o0 = p01 & 0xFFFF, o1 = p01 >> 16;
            uint32_t o8 = p89 & 0xFFFF, o9 = p89 >> 16;
            // B fragments (group g, 64 n, 16 k)
            uint32_t b[4][4];
#pragma unroll
            for (int bt = 0; bt < 4; bt++)
                ldsm4(b[bt], sb + (uint32_t)((g * 64 + 16 * bt) * BS2 + kci * 32) + b_offB);
            // A fragments by direct gather from h
            uint32_t a[2][4];
#pragma unroll
            for (int mt = 0; mt < 2; mt++) {
                const char* rp0 = pA + (pbase + msub + 16 * mt + qr) * RS;
                const char* rp1 = rp0 + 8 * RS;
                uint32_t h00 = *(const uint16_t*)(rp0 + o0);
                uint32_t h01 = *(const uint16_t*)(rp0 + o1);
                uint32_t h10 = *(const uint16_t*)(rp1 + o0);
                uint32_t h11 = *(const uint16_t*)(rp1 + o1);
                uint32_t h08 = *(const uint16_t*)(rp0 + o8);
                uint32_t h09 = *(const uint16_t*)(rp0 + o9);
                uint32_t h18 = *(const uint16_t*)(rp1 + o8);
                uint32_t h19 = *(const uint16_t*)(rp1 + o9);
                a[mt][0] = __byte_perm(h00, h01, 0x5410);
                a[mt][1] = __byte_perm(h10, h11, 0x5410);
                a[mt][2] = __byte_perm(h08, h09, 0x5410);
                a[mt][3] = __byte_perm(h18, h19, 0x5410);
            }
#pragma unroll
            for (int mt = 0; mt < 2; mt++)
#pragma unroll
                for (int nt = 0; nt < 8; nt++)
                    mma16816(cur[mt][nt], a[mt], &b[nt >> 1][(nt & 1) * 2]);
            // 2 deferred epilogue units per kci (16 over the pass)
            if (def) {
                int u = 2 * kci;
                epi_unit(*def, u >> 3, u & 7, dbase, dbias);
                u++;
                epi_unit(*def, u >> 3, u & 7, dbase, dbias);
            }
        }
    };

    // ---- prologue --------------------------------------------------------
    s_bias[0][tid] = g_bias[0][tid];
    s_bias[1][tid] = g_bias[1][tid];
    s_bias[2][tid] = g_bias[2][tid];
    if (tid < 16) s_bout[tid] = g_bout[tid];
    for (int c = tid; c < 768; c += NTHR)
        ((uint32_t*)s_boff)[c] = ((const uint32_t*)g_boff)[c];
    {
        const char* wsrc = (const char*)g_Wout_img;
        for (int c = tid; c < 528; c += NTHR)
            CP_ASYNC16(sW + c * 16, wsrc + c * 16);
        CP_COMMIT();                 // group: W image
    }
    issue_B(0);                      // level0 -> stage0
    load_x(blockIdx.x);

    float cA[2][8][4], cB[2][8][4];
    int ci = 0;                      // level counter mod 6 (stage = ci&1)

    for (int t = blockIdx.x; t < NTILES; t += GRID) {
        for (int l = 0; l < 3; l++) {
            __syncthreads();                       // S1: h/x + stage-free publish
            issue_B(ci + 1);                       // next level -> other stage
            CP_WAIT1();                            // B[l] resident
            __syncthreads();                       // S2: publish stage
            uint32_t sb = sB0 + (uint32_t)(ci & 1) * CHB;

            // pass0 rows 0-63; interleave epi of prev level rows 64-127 (cB)
            if (l > 0)
                run_pass(l, 0, sb, cA, &cB, 64, s_bias[l - 1]);
            else
                run_pass(l, 0, sb, cA, nullptr, 0, s_bias[0]);

            // S_D: pass0's interleaved epi writes (rows 64-127, all g-warps)
            // must be visible before pass1's gather reads those rows, and
            // pass0's gather reads of rows 0-63 must complete before pass1's
            // interleaved epi overwrites them. (Missing in R10 -> race.)
            __syncthreads();

            // pass1 rows 64-127; interleave epi of this level rows 0-63 (cA)
            run_pass(l, 64, sb, cB, &cA, 0, s_bias[l]);

            ci = (ci == 5) ? 0 : ci + 1;
        }

        __syncthreads();                           // all pass1-l2 reads done
        // exposed epilogue: level2 rows 64-127 (cB)
#pragma unroll
        for (int u = 0; u < 16; u++)
            epi_unit(cB, u >> 3, u & 7, 64, s_bias[2]);
        __syncthreads();                           // h3 complete

        // ---- final layer: out = h3 @ W_out + b_out (warp-per-16-rows) ----
        {
            float cf[2][4];
#pragma unroll
            for (int nt = 0; nt < 2; nt++)
#pragma unroll
                for (int q = 0; q < 4; q++) cf[nt][q] = 0.0f;
            int m0f = wid * 16;
#pragma unroll
            for (int kc = 0; kc < 16; kc++) {
                uint32_t a[4], b[4];
                ldsm4(a, sA + (uint32_t)(m0f * RS + kc * 32) + a_off528);
                ldsm4(b, sW + (uint32_t)(kc * 32) + b_off528);
                mma16816(cf[0], a, &b[0]);
                mma16816(cf[1], a, &b[2]);
            }
            float* po0 = out + ((size_t)t * 128 + m0f + qr) * 10;
            float* po1 = po0 + 80;   // +8 rows
#pragma unroll
            for (int nt = 0; nt < 2; nt++) {
                int n8 = nt * 8 + qc2;
                if (n8 < 10) {
                    po0[n8] = cf[nt][0] + s_bout[n8];
                    po1[n8] = cf[nt][2] + s_bout[n8];
                }
                if (n8 + 1 < 10) {
                    po0[n8 + 1] = cf[nt][1] + s_bout[n8 + 1];
                    po1[n8 + 1] = cf[nt][3] + s_bout[n8 + 1];
                }
            }
        }

        // next x tile into this warp's private rows (published by next S1)
        if (t + GRID < NTILES) load_x(t + GRID);
    }
    CP_WAIT0();
}

// ---------------- launch ----------------------------------------------------
extern "C" void kernel_launch(void* const* d_in, const int* in_sizes, int n_in,
                              void* d_out, int out_size) {
    const float* x     = (const float*)d_in[0];
    const int*   idx   = (const int*)  d_in[1];
    const float* W     = (const float*)d_in[2];
    const float* b     = (const float*)d_in[3];
    const float* W_out = (const float*)d_in[4];
    const float* b_out = (const float*)d_in[5];
    float* out = (float*)d_out;

    cudaFuncSetAttribute(fused_kernel, cudaFuncAttributeMaxDynamicSharedMemorySize, DYN_SMEM);

    prep_kernel<<<769, 256>>>(idx, W, W_out, b, b_out);
    fused_kernel<<<GRID, NTHR, DYN_SMEM>>>(x, out);
}